// round 12
// baseline (speedup 1.0000x reference)
#include <cuda_runtime.h>
#include <cuda_bf16.h>
#include <cstdint>
#include <math.h>

#define D_    256
#define HW_   1024
#define N_    32768
#define K_    1024
#define NELEM_ 8388608
#define BT    128               // xbf + dist token tile
#define BNQ   128               // dist codes per block (8 quadrants)
#define BTG   64                // gather tokens per block
#define EPSM  1e-3f

#define APITCH 264

// -------- device scratch --------
__device__ float          g_dist[N_ * (size_t)K_];  // 128 MiB
__device__ float4         g_q[N_ * 8];              // per-token per-quadrant (m1,m2,ki)
__device__ float          g_B[K_];
__device__ int            g_idx[N_];
__device__ int            g_counts[K_];
__device__ float          g_partials[N_ / BTG];
__device__ unsigned short g_Xb[N_ * D_];
__device__ unsigned short g_Eb[K_ * D_];

// -------- helpers --------
__device__ __forceinline__ unsigned short f2bf(float x) {
    __nv_bfloat16 b = __float2bfloat16(x);
    return *reinterpret_cast<unsigned short*>(&b);
}
__device__ __forceinline__ uint32_t smem_u32(const void* p) {
    uint32_t a;
    asm("{ .reg .u64 t; cvta.to.shared.u64 t, %1; cvt.u32.u64 %0, t; }" : "=r"(a) : "l"(p));
    return a;
}
__device__ __forceinline__ void ldsm_x4(uint32_t& r0, uint32_t& r1,
                                        uint32_t& r2, uint32_t& r3, uint32_t addr) {
    asm volatile("ldmatrix.sync.aligned.m8n8.x4.shared.b16 {%0,%1,%2,%3}, [%4];"
                 : "=r"(r0), "=r"(r1), "=r"(r2), "=r"(r3) : "r"(addr));
}
__device__ __forceinline__ void mma16816(float& c0, float& c1, float& c2, float& c3,
                                         uint32_t a0, uint32_t a1, uint32_t a2, uint32_t a3,
                                         uint32_t b0, uint32_t b1) {
    asm volatile(
        "mma.sync.aligned.m16n8k16.row.col.f32.bf16.bf16.f32 "
        "{%0,%1,%2,%3}, {%4,%5,%6,%7}, {%8,%9}, {%0,%1,%2,%3};"
        : "+f"(c0), "+f"(c1), "+f"(c2), "+f"(c3)
        : "r"(a0), "r"(a1), "r"(a2), "r"(a3), "r"(b0), "r"(b1));
}
__device__ __forceinline__ void top2_upd(float v, int k, float& m1, float& m2, int& ki) {
    if (v < m1) { m2 = m1; m1 = v; ki = k; }
    else if (v < m2) m2 = v;
}
__device__ __forceinline__ void top2_merge(float& m1, float& m2, int& ki,
                                           float bm1, float bm2, int bki) {
    float hi = fmaxf(m1, bm1);
    m2 = fminf(hi, fminf(m2, bm2));
    if (bm1 < m1 || (bm1 == m1 && bki < ki)) { m1 = bm1; ki = bki; }
}

// ---------------------------------------------------------
__global__ void init_kernel() {
    int i = blockIdx.x * blockDim.x + threadIdx.x;
    if (i < K_) g_counts[i] = 0;
}

__global__ void enorm_kernel(const float* __restrict__ E) {
    __shared__ double red[256];
    int k = blockIdx.x;
    float v = E[(size_t)k * D_ + threadIdx.x];
    red[threadIdx.x] = (double)v * (double)v;
    __syncthreads();
    for (int s = 128; s > 0; s >>= 1) {
        if (threadIdx.x < s) red[threadIdx.x] += red[threadIdx.x + s];
        __syncthreads();
    }
    if (threadIdx.x == 0) g_B[k] = (float)red[0];
}

__global__ void ebf_kernel(const float* __restrict__ E) {
    int k = blockIdx.x;
    g_Eb[k * D_ + threadIdx.x] = f2bf(E[(size_t)k * D_ + threadIdx.x]);
}

// ---------------------------------------------------------
__global__ void __launch_bounds__(256)
xbf_kernel(const float* __restrict__ IN) {
    extern __shared__ unsigned short sm[];   // [128 d][128 t]

    const int tid = threadIdx.x;
    const int n0  = blockIdx.x * BT;
    const int d0  = blockIdx.y * 128;
    const int b   = n0 >> 10;
    const int hw0 = n0 & (HW_ - 1);
    const float* inb = IN + (size_t)b * (D_ * HW_) + (size_t)d0 * HW_ + hw0;

    #pragma unroll
    for (int it = 0; it < 16; ++it) {
        int j  = it * 256 + tid;
        int t4 = j & 31;
        int d  = j >> 5;
        float4 v = *reinterpret_cast<const float4*>(inb + (size_t)d * HW_ + t4 * 4);
        uint32_t* p = reinterpret_cast<uint32_t*>(&sm[d * BT + t4 * 4]);
        p[0] = (uint32_t)f2bf(v.x) | ((uint32_t)f2bf(v.y) << 16);
        p[1] = (uint32_t)f2bf(v.z) | ((uint32_t)f2bf(v.w) << 16);
    }
    __syncthreads();

    const int t    = tid & 127;
    const int half = tid >> 7;
    #pragma unroll
    for (int c = 0; c < 8; ++c) {
        int dd = half * 64 + c * 8;
        unsigned short u[8];
        #pragma unroll
        for (int i = 0; i < 8; ++i) u[i] = sm[(dd + i) * BT + t];
        uint4 q;
        q.x = (uint32_t)u[0] | ((uint32_t)u[1] << 16);
        q.y = (uint32_t)u[2] | ((uint32_t)u[3] << 16);
        q.z = (uint32_t)u[4] | ((uint32_t)u[5] << 16);
        q.w = (uint32_t)u[6] | ((uint32_t)u[7] << 16);
        *reinterpret_cast<uint4*>(&g_Xb[(size_t)(n0 + t) * D_ + d0 + dd]) = q;
    }
}

// ---------------------------------------------------------
// HMMA distance GEMM: round-8 config EXACTLY (128 tok x 128 codes, 256 thr,
// single-buffered frags) + fused per-row top-2 epilogue -> g_q.
#define SMEM_MMA (2 * BT * APITCH * 2 + 2 * 128 * 16)

__global__ void __launch_bounds__(256, 1)
dist_mma_kernel() {
    extern __shared__ char sraw[];
    unsigned short* As = reinterpret_cast<unsigned short*>(sraw);    // [128][264]
    unsigned short* Bs = As + BT * APITCH;                            // [128][264]
    float4* sq = reinterpret_cast<float4*>(sraw + 2 * BT * APITCH * 2); // [2 wn][128]

    const int tid  = threadIdx.x;
    const int wid  = tid >> 5;
    const int lane = tid & 31;
    const int wm   = wid & 3;        // 4 M-groups x 32 tokens
    const int wn   = wid >> 2;       // 2 N-groups x 64 codes
    const int n0   = blockIdx.x * BT;
    const int kq   = blockIdx.y;     // 8 quadrants of 128 codes

    #pragma unroll
    for (int it = 0; it < 16; ++it) {
        int idx = it * 256 + tid;
        int row = idx >> 5, c = idx & 31;
        *reinterpret_cast<uint4*>(&As[row * APITCH + c * 8]) =
            *reinterpret_cast<const uint4*>(&g_Xb[(size_t)(n0 + row) * D_ + c * 8]);
        *reinterpret_cast<uint4*>(&Bs[row * APITCH + c * 8]) =
            *reinterpret_cast<const uint4*>(&g_Eb[(size_t)(kq * BNQ + row) * D_ + c * 8]);
    }
    __syncthreads();

    const uint32_t aBase = smem_u32(As);
    const uint32_t bBase = smem_u32(Bs);

    float acc[2][8][4];
    #pragma unroll
    for (int i = 0; i < 2; ++i)
        #pragma unroll
        for (int j = 0; j < 8; ++j)
            #pragma unroll
            for (int c = 0; c < 4; ++c) acc[i][j][c] = 0.0f;

    const int aRow = wm * 32 + (lane & 15);
    const uint32_t aOff = aBase + (uint32_t)aRow * (APITCH * 2) + (uint32_t)(lane >> 4) * 16;
    const int bRow = wn * 64 + (lane & 7) + ((lane >> 4) << 3);
    const uint32_t bOff = bBase + (uint32_t)bRow * (APITCH * 2) + (uint32_t)((lane >> 3) & 1) * 16;

    #pragma unroll
    for (int ks = 0; ks < D_ / 16; ++ks) {
        const uint32_t kb = ks * 32;
        uint32_t a[2][4];
        ldsm_x4(a[0][0], a[0][1], a[0][2], a[0][3], aOff + kb);
        ldsm_x4(a[1][0], a[1][1], a[1][2], a[1][3], aOff + 16 * (APITCH * 2) + kb);
        uint32_t bfr[8][2];
        #pragma unroll
        for (int ng = 0; ng < 4; ++ng) {
            uint32_t r0, r1, r2, r3;
            ldsm_x4(r0, r1, r2, r3, bOff + (uint32_t)ng * 16 * (APITCH * 2) + kb);
            bfr[2 * ng][0] = r0; bfr[2 * ng][1] = r1;
            bfr[2 * ng + 1][0] = r2; bfr[2 * ng + 1][1] = r3;
        }
        #pragma unroll
        for (int msub = 0; msub < 2; ++msub)
            #pragma unroll
            for (int nn = 0; nn < 8; ++nn)
                mma16816(acc[msub][nn][0], acc[msub][nn][1],
                         acc[msub][nn][2], acc[msub][nn][3],
                         a[msub][0], a[msub][1], a[msub][2], a[msub][3],
                         bfr[nn][0], bfr[nn][1]);
    }

    // epilogue: d~ = en - 2*dot, write g_dist, fused per-row top-2
    #pragma unroll
    for (int msub = 0; msub < 2; ++msub) {
        int rowL = wm * 32 + msub * 16 + (lane >> 2);
        float m1a = 3.4e38f, m2a = 3.4e38f; int kia = 0;
        float m1b = 3.4e38f, m2b = 3.4e38f; int kib = 0;
        #pragma unroll
        for (int nn = 0; nn < 8; ++nn) {
            int code = kq * BNQ + wn * 64 + nn * 8 + 2 * (lane & 3);
            float2 en = *reinterpret_cast<const float2*>(&g_B[code]);
            float2 lo, hi;
            lo.x = fmaf(-2.0f, acc[msub][nn][0], en.x);
            lo.y = fmaf(-2.0f, acc[msub][nn][1], en.y);
            hi.x = fmaf(-2.0f, acc[msub][nn][2], en.x);
            hi.y = fmaf(-2.0f, acc[msub][nn][3], en.y);
            *reinterpret_cast<float2*>(&g_dist[(size_t)(n0 + rowL) * K_ + code]) = lo;
            *reinterpret_cast<float2*>(&g_dist[(size_t)(n0 + rowL + 8) * K_ + code]) = hi;
            top2_upd(lo.x, code,     m1a, m2a, kia);
            top2_upd(lo.y, code + 1, m1a, m2a, kia);
            top2_upd(hi.x, code,     m1b, m2b, kib);
            top2_upd(hi.y, code + 1, m1b, m2b, kib);
        }
        #pragma unroll
        for (int off = 1; off <= 2; off <<= 1) {
            float o1 = __shfl_xor_sync(0xFFFFFFFFu, m1a, off);
            float o2 = __shfl_xor_sync(0xFFFFFFFFu, m2a, off);
            int   oi = __shfl_xor_sync(0xFFFFFFFFu, kia, off);
            top2_merge(m1a, m2a, kia, o1, o2, oi);
            o1 = __shfl_xor_sync(0xFFFFFFFFu, m1b, off);
            o2 = __shfl_xor_sync(0xFFFFFFFFu, m2b, off);
            oi = __shfl_xor_sync(0xFFFFFFFFu, kib, off);
            top2_merge(m1b, m2b, kib, o1, o2, oi);
        }
        if ((lane & 3) == 0) {
            sq[wn * 128 + rowL]     = make_float4(m1a, m2a, __int_as_float(kia), 0.0f);
            sq[wn * 128 + rowL + 8] = make_float4(m1b, m2b, __int_as_float(kib), 0.0f);
        }
    }
    __syncthreads();

    if (tid < 128) {
        float4 q0 = sq[tid];
        float4 q1 = sq[128 + tid];
        float m1 = q0.x, m2 = q0.y; int ki = __float_as_int(q0.z);
        top2_merge(m1, m2, ki, q1.x, q1.y, __float_as_int(q1.z));
        g_q[(size_t)(n0 + tid) * 8 + kq] = make_float4(m1, m2, __int_as_float(ki), 0.0f);
    }
}

// ---------------------------------------------------------
__device__ __forceinline__ unsigned order_f(float f) {
    unsigned u = __float_as_uint(f);
    return (u & 0x80000000u) ? ~u : (u | 0x80000000u);
}

// select v4: merge 8 quadrant partials (4 MiB); slow path re-reads row.
__global__ void __launch_bounds__(256)
select_kernel(const float* __restrict__ IN, const float* __restrict__ E) {
    const int lane = threadIdx.x & 31;
    const int n = blockIdx.x * 256 + threadIdx.x;

    float4 q0 = g_q[(size_t)n * 8];
    float m1 = q0.x, m2 = q0.y; int ki = __float_as_int(q0.z);
    #pragma unroll
    for (int i = 1; i < 8; ++i) {
        float4 q = g_q[(size_t)n * 8 + i];
        top2_merge(m1, m2, ki, q.x, q.y, __float_as_int(q.z));
    }

    int k_final = ki;
    bool slow = (m2 <= m1 + EPSM);

    unsigned fm = __ballot_sync(0xFFFFFFFFu, slow);
    while (fm) {
        int leader = __ffs(fm) - 1;
        fm &= fm - 1;
        int nt = __shfl_sync(0xFFFFFFFFu, n, leader);
        float thresh = __shfl_sync(0xFFFFFFFFu, m1, leader) + EPSM;

        const int b = nt >> 10, hw = nt & (HW_ - 1);
        const float* xb = IN + (size_t)b * (D_ * HW_) + hw;
        const float4* dr4 = reinterpret_cast<const float4*>(g_dist + (size_t)nt * K_);

        float xr[8];
        #pragma unroll
        for (int t = 0; t < 8; ++t)
            xr[t] = xb[(size_t)(lane + 32 * t) * HW_];

        double a = 0.0;
        #pragma unroll
        for (int t = 0; t < 8; ++t) a += (double)xr[t] * (double)xr[t];
        #pragma unroll
        for (int off = 16; off > 0; off >>= 1)
            a += __shfl_xor_sync(0xFFFFFFFFu, a, off);
        float Af = (float)a;

        unsigned cmask = 0;
        #pragma unroll
        for (int j = 0; j < 8; ++j) {
            float4 v = dr4[lane + 32 * j];
            if (v.x <= thresh) cmask |= 1u << (4 * j);
            if (v.y <= thresh) cmask |= 1u << (4 * j + 1);
            if (v.z <= thresh) cmask |= 1u << (4 * j + 2);
            if (v.w <= thresh) cmask |= 1u << (4 * j + 3);
        }

        unsigned long long key = 0xFFFFFFFFFFFFFFFFull;
        while (true) {
            unsigned ball = __ballot_sync(0xFFFFFFFFu, cmask != 0);
            if (!ball) break;
            int cl = __ffs(ball) - 1;
            unsigned lm = __shfl_sync(0xFFFFFFFFu, cmask, cl);
            int bit = __ffs(lm) - 1;
            int k = 4 * (cl + 32 * (bit >> 2)) + (bit & 3);
            if (lane == cl) cmask &= cmask - 1;

            const float* er = E + (size_t)k * D_;
            double dot = 0.0;
            #pragma unroll
            for (int t = 0; t < 8; ++t)
                dot += (double)xr[t] * (double)er[lane + 32 * t];
            #pragma unroll
            for (int off = 16; off > 0; off >>= 1)
                dot += __shfl_xor_sync(0xFFFFFFFFu, dot, off);

            float Mf = (float)dot;
            float T  = Af + __ldg(&g_B[k]);   // fl32
            float ds = T - 2.0f * Mf;         // fl32
            unsigned long long kk =
                ((unsigned long long)order_f(ds) << 32) | (unsigned)k;
            if (kk < key) key = kk;
        }
        if (lane == leader) k_final = (int)(unsigned)key;
    }

    g_idx[n] = k_final;
    atomicAdd(&g_counts[k_final], 1);
}

// ---------------------------------------------------------
__global__ void __launch_bounds__(256)
gather_kernel(const float* __restrict__ IN, const float* __restrict__ E,
              float* __restrict__ OUT) {
    extern __shared__ float fsm[];
    float* qs   = fsm;                          // [64][257]
    int*   sidx = (int*)(fsm + BTG * 257);
    float* red  = fsm + BTG * 257 + BTG;

    const int tid = threadIdx.x;
    const int n0  = blockIdx.x * BTG;

    if (tid < BTG) sidx[tid] = g_idx[n0 + tid];
    __syncthreads();

    #pragma unroll 4
    for (int it = 0; it < BTG; ++it)
        qs[it * 257 + tid] = E[(size_t)sidx[it] * D_ + tid];
    __syncthreads();

    const int b = n0 >> 10, hw0 = n0 & (HW_ - 1);
    const size_t base = (size_t)b * (D_ * HW_) + hw0;
    float lsum = 0.0f;
    #pragma unroll 4
    for (int it = 0; it < 64; ++it) {
        int j = it * 256 + tid;
        int d = j >> 6;
        int t = j & 63;
        size_t a = base + (size_t)d * HW_ + t;
        float x = IN[a];
        float q = qs[t * 257 + d];
        OUT[a] = q;
        float df = q - x;
        lsum += df * df;
    }
    red[tid] = lsum;
    __syncthreads();
    for (int s = 128; s > 0; s >>= 1) {
        if (tid < s) red[tid] += red[tid + s];
        __syncthreads();
    }
    if (tid == 0) g_partials[blockIdx.x] = red[0];
}

// ---------------------------------------------------------
__global__ void finalize_kernel(float* __restrict__ OUT, int out_size) {
    __shared__ float red[256];
    int tid = threadIdx.x;

    red[tid] = g_partials[tid] + g_partials[tid + 256];
    __syncthreads();
    for (int s = 128; s > 0; s >>= 1) {
        if (tid < s) red[tid] += red[tid + s];
        __syncthreads();
    }
    float loss = 1.25f * red[0] / (float)NELEM_;
    __syncthreads();

    float ps = 0.0f;
    for (int i = tid; i < K_; i += 256) {
        float p = (float)g_counts[i] / (float)N_;
        ps += p * logf(p + 1e-10f);
    }
    red[tid] = ps;
    __syncthreads();
    for (int s = 128; s > 0; s >>= 1) {
        if (tid < s) red[tid] += red[tid + s];
        __syncthreads();
    }
    if (tid == 0) {
        float perp = expf(-red[0]);
        if (out_size > NELEM_)     OUT[NELEM_]     = loss;
        if (out_size > NELEM_ + 1) OUT[NELEM_ + 1] = perp;
    }
}

// ---------------------------------------------------------
extern "C" void kernel_launch(void* const* d_in, const int* in_sizes, int n_in,
                              void* d_out, int out_size) {
    const float* IN = (const float*)d_in[0];
    const float* E  = (const float*)d_in[1];
    float* OUT = (float*)d_out;

    const int smemX = 128 * BT * (int)sizeof(unsigned short);        // 32768
    const int smemM = SMEM_MMA;                                      // 139264
    const int smemC = (BTG * 257 + BTG + 256) * (int)sizeof(float);  // 67072
    cudaFuncSetAttribute(xbf_kernel,      cudaFuncAttributeMaxDynamicSharedMemorySize, smemX);
    cudaFuncSetAttribute(dist_mma_kernel, cudaFuncAttributeMaxDynamicSharedMemorySize, smemM);
    cudaFuncSetAttribute(gather_kernel,   cudaFuncAttributeMaxDynamicSharedMemorySize, smemC);

    init_kernel<<<4, 256>>>();
    ebf_kernel<<<K_, 256>>>(E);
    enorm_kernel<<<K_, 256>>>(E);
    xbf_kernel<<<dim3(N_ / BT, 2), 256, smemX>>>(IN);
    dist_mma_kernel<<<dim3(N_ / BT, K_ / BNQ), 256, smemM>>>();
    select_kernel<<<N_ / 256, 256>>>(IN, E);
    gather_kernel<<<N_ / BTG, 256, smemC>>>(IN, E, OUT);
    finalize_kernel<<<1, 256>>>(OUT, out_size);
}

// round 13
// speedup vs baseline: 1.2971x; 1.2971x over previous
#include <cuda_runtime.h>
#include <cuda_bf16.h>
#include <cuda_fp16.h>
#include <cstdint>
#include <math.h>

#define D_    256
#define HW_   1024
#define N_    32768
#define K_    1024
#define NELEM_ 8388608
#define BT    128
#define BNQ   128
#define EPSM  1e-3f

#define APITCH 264

// -------- device scratch --------
__device__ __half         g_dist[N_ * (size_t)K_];  // 64 MiB fp16 approx distances
__device__ float          g_B[K_];
__device__ int            g_idx[N_];
__device__ int            g_counts[K_];
__device__ float          g_partials[N_ / BT];
__device__ unsigned short g_Xb[N_ * D_];
__device__ unsigned short g_Eb[K_ * D_];

// -------- helpers --------
__device__ __forceinline__ unsigned short f2bf(float x) {
    __nv_bfloat16 b = __float2bfloat16(x);
    return *reinterpret_cast<unsigned short*>(&b);
}
__device__ __forceinline__ uint32_t smem_u32(const void* p) {
    uint32_t a;
    asm("{ .reg .u64 t; cvta.to.shared.u64 t, %1; cvt.u32.u64 %0, t; }" : "=r"(a) : "l"(p));
    return a;
}
__device__ __forceinline__ void ldsm_x4(uint32_t& r0, uint32_t& r1,
                                        uint32_t& r2, uint32_t& r3, uint32_t addr) {
    asm volatile("ldmatrix.sync.aligned.m8n8.x4.shared.b16 {%0,%1,%2,%3}, [%4];"
                 : "=r"(r0), "=r"(r1), "=r"(r2), "=r"(r3) : "r"(addr));
}
__device__ __forceinline__ void mma16816(float& c0, float& c1, float& c2, float& c3,
                                         uint32_t a0, uint32_t a1, uint32_t a2, uint32_t a3,
                                         uint32_t b0, uint32_t b1) {
    asm volatile(
        "mma.sync.aligned.m16n8k16.row.col.f32.bf16.bf16.f32 "
        "{%0,%1,%2,%3}, {%4,%5,%6,%7}, {%8,%9}, {%0,%1,%2,%3};"
        : "+f"(c0), "+f"(c1), "+f"(c2), "+f"(c3)
        : "r"(a0), "r"(a1), "r"(a2), "r"(a3), "r"(b0), "r"(b1));
}

// ---------------------------------------------------------
__global__ void init_kernel() {
    int i = blockIdx.x * blockDim.x + threadIdx.x;
    if (i < K_) g_counts[i] = 0;
}

__global__ void enorm_kernel(const float* __restrict__ E) {
    __shared__ double red[256];
    int k = blockIdx.x;
    float v = E[(size_t)k * D_ + threadIdx.x];
    red[threadIdx.x] = (double)v * (double)v;
    __syncthreads();
    for (int s = 128; s > 0; s >>= 1) {
        if (threadIdx.x < s) red[threadIdx.x] += red[threadIdx.x + s];
        __syncthreads();
    }
    if (threadIdx.x == 0) g_B[k] = (float)red[0];
}

__global__ void ebf_kernel(const float* __restrict__ E) {
    int k = blockIdx.x;
    g_Eb[k * D_ + threadIdx.x] = f2bf(E[(size_t)k * D_ + threadIdx.x]);
}

// ---------------------------------------------------------
__global__ void __launch_bounds__(256)
xbf_kernel(const float* __restrict__ IN) {
    extern __shared__ unsigned short sm[];   // [128 d][128 t]

    const int tid = threadIdx.x;
    const int n0  = blockIdx.x * BT;
    const int d0  = blockIdx.y * 128;
    const int b   = n0 >> 10;
    const int hw0 = n0 & (HW_ - 1);
    const float* inb = IN + (size_t)b * (D_ * HW_) + (size_t)d0 * HW_ + hw0;

    #pragma unroll
    for (int it = 0; it < 16; ++it) {
        int j  = it * 256 + tid;
        int t4 = j & 31;
        int d  = j >> 5;
        float4 v = *reinterpret_cast<const float4*>(inb + (size_t)d * HW_ + t4 * 4);
        uint32_t* p = reinterpret_cast<uint32_t*>(&sm[d * BT + t4 * 4]);
        p[0] = (uint32_t)f2bf(v.x) | ((uint32_t)f2bf(v.y) << 16);
        p[1] = (uint32_t)f2bf(v.z) | ((uint32_t)f2bf(v.w) << 16);
    }
    __syncthreads();

    const int t    = tid & 127;
    const int half = tid >> 7;
    #pragma unroll
    for (int c = 0; c < 8; ++c) {
        int dd = half * 64 + c * 8;
        unsigned short u[8];
        #pragma unroll
        for (int i = 0; i < 8; ++i) u[i] = sm[(dd + i) * BT + t];
        uint4 q;
        q.x = (uint32_t)u[0] | ((uint32_t)u[1] << 16);
        q.y = (uint32_t)u[2] | ((uint32_t)u[3] << 16);
        q.z = (uint32_t)u[4] | ((uint32_t)u[5] << 16);
        q.w = (uint32_t)u[6] | ((uint32_t)u[7] << 16);
        *reinterpret_cast<uint4*>(&g_Xb[(size_t)(n0 + t) * D_ + d0 + dd]) = q;
    }
}

// ---------------------------------------------------------
// HMMA distance GEMM — round-8 structure EXACTLY; only the stores are fp16.
#define SMEM_MMA (2 * BT * APITCH * 2)

__global__ void __launch_bounds__(256, 1)
dist_mma_kernel() {
    extern __shared__ unsigned short sAB[];
    unsigned short* As = sAB;                    // [128 tok][264]
    unsigned short* Bs = sAB + BT * APITCH;      // [128 code][264]

    const int tid  = threadIdx.x;
    const int wid  = tid >> 5;
    const int lane = tid & 31;
    const int wm   = wid & 3;
    const int wn   = wid >> 2;
    const int n0   = blockIdx.x * BT;
    const int kq   = blockIdx.y;

    #pragma unroll
    for (int it = 0; it < 16; ++it) {
        int idx = it * 256 + tid;
        int row = idx >> 5, c = idx & 31;
        *reinterpret_cast<uint4*>(&As[row * APITCH + c * 8]) =
            *reinterpret_cast<const uint4*>(&g_Xb[(size_t)(n0 + row) * D_ + c * 8]);
        *reinterpret_cast<uint4*>(&Bs[row * APITCH + c * 8]) =
            *reinterpret_cast<const uint4*>(&g_Eb[(size_t)(kq * BNQ + row) * D_ + c * 8]);
    }
    __syncthreads();

    const uint32_t aBase = smem_u32(As);
    const uint32_t bBase = smem_u32(Bs);

    float acc[2][8][4];
    #pragma unroll
    for (int i = 0; i < 2; ++i)
        #pragma unroll
        for (int j = 0; j < 8; ++j)
            #pragma unroll
            for (int c = 0; c < 4; ++c) acc[i][j][c] = 0.0f;

    const int aRow = wm * 32 + (lane & 15);
    const uint32_t aOff = aBase + (uint32_t)aRow * (APITCH * 2) + (uint32_t)(lane >> 4) * 16;
    const int bRow = wn * 64 + (lane & 7) + ((lane >> 4) << 3);
    const uint32_t bOff = bBase + (uint32_t)bRow * (APITCH * 2) + (uint32_t)((lane >> 3) & 1) * 16;

    #pragma unroll
    for (int ks = 0; ks < D_ / 16; ++ks) {
        const uint32_t kb = ks * 32;
        uint32_t a[2][4];
        ldsm_x4(a[0][0], a[0][1], a[0][2], a[0][3], aOff + kb);
        ldsm_x4(a[1][0], a[1][1], a[1][2], a[1][3], aOff + 16 * (APITCH * 2) + kb);
        uint32_t bfr[8][2];
        #pragma unroll
        for (int ng = 0; ng < 4; ++ng) {
            uint32_t r0, r1, r2, r3;
            ldsm_x4(r0, r1, r2, r3, bOff + (uint32_t)ng * 16 * (APITCH * 2) + kb);
            bfr[2 * ng][0] = r0; bfr[2 * ng][1] = r1;
            bfr[2 * ng + 1][0] = r2; bfr[2 * ng + 1][1] = r3;
        }
        #pragma unroll
        for (int msub = 0; msub < 2; ++msub)
            #pragma unroll
            for (int nn = 0; nn < 8; ++nn)
                mma16816(acc[msub][nn][0], acc[msub][nn][1],
                         acc[msub][nn][2], acc[msub][nn][3],
                         a[msub][0], a[msub][1], a[msub][2], a[msub][3],
                         bfr[nn][0], bfr[nn][1]);
    }

    // epilogue: d~ = en - 2*dot, fp16 stores (4 B each, same count as r8)
    #pragma unroll
    for (int msub = 0; msub < 2; ++msub) {
        int tok = n0 + wm * 32 + msub * 16 + (lane >> 2);
        #pragma unroll
        for (int nn = 0; nn < 8; ++nn) {
            int code = kq * BNQ + wn * 64 + nn * 8 + 2 * (lane & 3);
            float2 en = *reinterpret_cast<const float2*>(&g_B[code]);
            float2 lo, hi;
            lo.x = fmaf(-2.0f, acc[msub][nn][0], en.x);
            lo.y = fmaf(-2.0f, acc[msub][nn][1], en.y);
            hi.x = fmaf(-2.0f, acc[msub][nn][2], en.x);
            hi.y = fmaf(-2.0f, acc[msub][nn][3], en.y);
            *reinterpret_cast<__half2*>(&g_dist[(size_t)tok * K_ + code]) =
                __float22half2_rn(lo);
            *reinterpret_cast<__half2*>(&g_dist[(size_t)(tok + 8) * K_ + code]) =
                __float22half2_rn(hi);
        }
    }
}

// ---------------------------------------------------------
__device__ __forceinline__ unsigned order_f(float f) {
    unsigned u = __float_as_uint(f);
    return (u & 0x80000000u) ? ~u : (u | 0x80000000u);
}

// select v3 structure (one warp per token), fp16 row reads.
__global__ void __launch_bounds__(256)
select_kernel(const float* __restrict__ IN, const float* __restrict__ E) {
    const int warp = threadIdx.x >> 5;
    const int lane = threadIdx.x & 31;
    const int n = blockIdx.x * 8 + warp;

    const uint4* dr4 = reinterpret_cast<const uint4*>(g_dist + (size_t)n * K_);

    uint4 v[4];
    #pragma unroll
    for (int j = 0; j < 4; ++j) v[j] = dr4[lane + 32 * j];   // 4 independent LDG.128

    float m1 = 3.4e38f, m2 = 3.4e38f;
    int ki = 0;
    #pragma unroll
    for (int j = 0; j < 4; ++j) {
        uint32_t w[4] = {v[j].x, v[j].y, v[j].z, v[j].w};
        int kb = 8 * (lane + 32 * j);
        #pragma unroll
        for (int q = 0; q < 4; ++q) {
            float2 f = __half22float2(*reinterpret_cast<const __half2*>(&w[q]));
            if (f.x < m1) { m2 = m1; m1 = f.x; ki = kb + 2 * q; }
            else if (f.x < m2) m2 = f.x;
            if (f.y < m1) { m2 = m1; m1 = f.y; ki = kb + 2 * q + 1; }
            else if (f.y < m2) m2 = f.y;
        }
    }
    #pragma unroll
    for (int off = 16; off > 0; off >>= 1) {
        float o1 = __shfl_xor_sync(0xFFFFFFFFu, m1, off);
        float o2 = __shfl_xor_sync(0xFFFFFFFFu, m2, off);
        int   oi = __shfl_xor_sync(0xFFFFFFFFu, ki, off);
        float hi  = fmaxf(m1, o1);
        float nm2 = fminf(hi, fminf(m2, o2));
        if (o1 < m1 || (o1 == m1 && oi < ki)) ki = oi;
        m1 = fminf(m1, o1);
        m2 = nm2;
    }
    const float thresh = m1 + EPSM;

    int k_final = ki;
    if (m2 <= thresh) {
        const int b = n >> 10, hw = n & (HW_ - 1);
        const float* xb = IN + (size_t)b * (D_ * HW_) + hw;

        float xr[8];
        #pragma unroll
        for (int t = 0; t < 8; ++t)
            xr[t] = xb[(size_t)(lane + 32 * t) * HW_];

        double a = 0.0;
        #pragma unroll
        for (int t = 0; t < 8; ++t) a += (double)xr[t] * (double)xr[t];
        #pragma unroll
        for (int off = 16; off > 0; off >>= 1)
            a += __shfl_xor_sync(0xFFFFFFFFu, a, off);
        float Af = (float)a;

        unsigned cmask = 0;   // bit 8j+p -> code 8*(lane+32j)+p
        #pragma unroll
        for (int j = 0; j < 4; ++j) {
            uint32_t w[4] = {v[j].x, v[j].y, v[j].z, v[j].w};
            #pragma unroll
            for (int q = 0; q < 4; ++q) {
                float2 f = __half22float2(*reinterpret_cast<const __half2*>(&w[q]));
                if (f.x <= thresh) cmask |= 1u << (8 * j + 2 * q);
                if (f.y <= thresh) cmask |= 1u << (8 * j + 2 * q + 1);
            }
        }

        unsigned long long key = 0xFFFFFFFFFFFFFFFFull;
        while (true) {
            unsigned ball = __ballot_sync(0xFFFFFFFFu, cmask != 0);
            if (!ball) break;
            int cl = __ffs(ball) - 1;
            unsigned lm = __shfl_sync(0xFFFFFFFFu, cmask, cl);
            int bit = __ffs(lm) - 1;
            int k = 8 * (cl + 32 * (bit >> 3)) + (bit & 7);
            if (lane == cl) cmask &= cmask - 1;

            const float* er = E + (size_t)k * D_;
            double dot = 0.0;
            #pragma unroll
            for (int t = 0; t < 8; ++t)
                dot += (double)xr[t] * (double)er[lane + 32 * t];
            #pragma unroll
            for (int off = 16; off > 0; off >>= 1)
                dot += __shfl_xor_sync(0xFFFFFFFFu, dot, off);

            float Mf = (float)dot;
            float T  = Af + __ldg(&g_B[k]);   // fl32
            float ds = T - 2.0f * Mf;         // fl32
            unsigned long long kk =
                ((unsigned long long)order_f(ds) << 32) | (unsigned)k;
            if (kk < key) key = kk;
        }
        k_final = (int)(unsigned)key;
    }

    if (lane == 0) {
        g_idx[n] = k_final;
        atomicAdd(&g_counts[k_final], 1);
    }
}

// ---------------------------------------------------------
__global__ void __launch_bounds__(256, 1)
gather_kernel(const float* __restrict__ IN, const float* __restrict__ E,
              float* __restrict__ OUT) {
    extern __shared__ float fsm[];
    float* qs   = fsm;                          // [128][257]
    int*   sidx = (int*)(fsm + 128 * 257);
    float* red  = fsm + 128 * 257 + 128;

    const int tid = threadIdx.x;
    const int n0  = blockIdx.x * BT;

    if (tid < BT) sidx[tid] = g_idx[n0 + tid];
    __syncthreads();

    #pragma unroll 4
    for (int it = 0; it < BT; ++it)
        qs[it * 257 + tid] = E[(size_t)sidx[it] * D_ + tid];
    __syncthreads();

    const int b = n0 >> 10, hw0 = n0 & (HW_ - 1);
    const size_t base = (size_t)b * (D_ * HW_) + hw0;
    float lsum = 0.0f;
    #pragma unroll 4
    for (int it = 0; it < 128; ++it) {
        int j = it * 256 + tid;
        int d = j >> 7;
        int t = j & 127;
        size_t a = base + (size_t)d * HW_ + t;
        float x = IN[a];
        float q = qs[t * 257 + d];
        OUT[a] = q;
        float df = q - x;
        lsum += df * df;
    }
    red[tid] = lsum;
    __syncthreads();
    for (int s = 128; s > 0; s >>= 1) {
        if (tid < s) red[tid] += red[tid + s];
        __syncthreads();
    }
    if (tid == 0) g_partials[blockIdx.x] = red[0];
}

// ---------------------------------------------------------
__global__ void finalize_kernel(float* __restrict__ OUT, int out_size) {
    __shared__ float red[256];
    int tid = threadIdx.x;

    red[tid] = g_partials[tid];
    __syncthreads();
    for (int s = 128; s > 0; s >>= 1) {
        if (tid < s) red[tid] += red[tid + s];
        __syncthreads();
    }
    float loss = 1.25f * red[0] / (float)NELEM_;
    __syncthreads();

    float ps = 0.0f;
    for (int i = tid; i < K_; i += 256) {
        float p = (float)g_counts[i] / (float)N_;
        ps += p * logf(p + 1e-10f);
    }
    red[tid] = ps;
    __syncthreads();
    for (int s = 128; s > 0; s >>= 1) {
        if (tid < s) red[tid] += red[tid + s];
        __syncthreads();
    }
    if (tid == 0) {
        float perp = expf(-red[0]);
        if (out_size > NELEM_)     OUT[NELEM_]     = loss;
        if (out_size > NELEM_ + 1) OUT[NELEM_ + 1] = perp;
    }
}

// ---------------------------------------------------------
extern "C" void kernel_launch(void* const* d_in, const int* in_sizes, int n_in,
                              void* d_out, int out_size) {
    const float* IN = (const float*)d_in[0];
    const float* E  = (const float*)d_in[1];
    float* OUT = (float*)d_out;

    const int smemX = 128 * BT * (int)sizeof(unsigned short);        // 32768
    const int smemM = SMEM_MMA;                                      // 135168
    const int smemC = (128 * 257 + 128 + 256) * (int)sizeof(float);  // 133120
    cudaFuncSetAttribute(xbf_kernel,      cudaFuncAttributeMaxDynamicSharedMemorySize, smemX);
    cudaFuncSetAttribute(dist_mma_kernel, cudaFuncAttributeMaxDynamicSharedMemorySize, smemM);
    cudaFuncSetAttribute(gather_kernel,   cudaFuncAttributeMaxDynamicSharedMemorySize, smemC);

    init_kernel<<<4, 256>>>();
    ebf_kernel<<<K_, 256>>>(E);
    enorm_kernel<<<K_, 256>>>(E);
    xbf_kernel<<<dim3(N_ / BT, 2), 256, smemX>>>(IN);
    dist_mma_kernel<<<dim3(N_ / BT, K_ / BNQ), 256, smemM>>>();
    select_kernel<<<N_ / 8, 256>>>(IN, E);
    gather_kernel<<<N_ / BT, 256, smemC>>>(IN, E, OUT);
    finalize_kernel<<<1, 256>>>(OUT, out_size);
}

// round 14
// speedup vs baseline: 1.4180x; 1.0932x over previous
#include <cuda_runtime.h>
#include <cuda_bf16.h>
#include <cuda_fp16.h>
#include <cstdint>
#include <math.h>

#define D_    256
#define HW_   1024
#define N_    32768
#define K_    1024
#define NELEM_ 8388608
#define BT    128
#define BNQ   128
#define BTG   64
#define EPSM  1e-3f

#define APITCH 264

// -------- device scratch --------
__device__ __half         g_dist[N_ * (size_t)K_];  // 64 MiB fp16 approx distances
__device__ float          g_B[K_];
__device__ int            g_idx[N_];
__device__ int            g_counts[K_];
__device__ float          g_partials[N_ / BTG];
__device__ unsigned short g_Xb[N_ * D_];
__device__ unsigned short g_Eb[K_ * D_];

// -------- helpers --------
__device__ __forceinline__ unsigned short f2bf(float x) {
    __nv_bfloat16 b = __float2bfloat16(x);
    return *reinterpret_cast<unsigned short*>(&b);
}
__device__ __forceinline__ uint32_t smem_u32(const void* p) {
    uint32_t a;
    asm("{ .reg .u64 t; cvta.to.shared.u64 t, %1; cvt.u32.u64 %0, t; }" : "=r"(a) : "l"(p));
    return a;
}
__device__ __forceinline__ void ldsm_x4(uint32_t& r0, uint32_t& r1,
                                        uint32_t& r2, uint32_t& r3, uint32_t addr) {
    asm volatile("ldmatrix.sync.aligned.m8n8.x4.shared.b16 {%0,%1,%2,%3}, [%4];"
                 : "=r"(r0), "=r"(r1), "=r"(r2), "=r"(r3) : "r"(addr));
}
__device__ __forceinline__ void mma16816(float& c0, float& c1, float& c2, float& c3,
                                         uint32_t a0, uint32_t a1, uint32_t a2, uint32_t a3,
                                         uint32_t b0, uint32_t b1) {
    asm volatile(
        "mma.sync.aligned.m16n8k16.row.col.f32.bf16.bf16.f32 "
        "{%0,%1,%2,%3}, {%4,%5,%6,%7}, {%8,%9}, {%0,%1,%2,%3};"
        : "+f"(c0), "+f"(c1), "+f"(c2), "+f"(c3)
        : "r"(a0), "r"(a1), "r"(a2), "r"(a3), "r"(b0), "r"(b1));
}

// ---------------------------------------------------------
// Merged prep: per code k -> g_Eb (bf16), g_B (f64 norm), g_counts=0.
__global__ void prep_kernel(const float* __restrict__ E) {
    __shared__ double red[256];
    int k = blockIdx.x;
    float v = E[(size_t)k * D_ + threadIdx.x];
    g_Eb[k * D_ + threadIdx.x] = f2bf(v);
    red[threadIdx.x] = (double)v * (double)v;
    __syncthreads();
    for (int s = 128; s > 0; s >>= 1) {
        if (threadIdx.x < s) red[threadIdx.x] += red[threadIdx.x + s];
        __syncthreads();
    }
    if (threadIdx.x == 0) {
        g_B[k] = (float)red[0];
        g_counts[k] = 0;
    }
}

// ---------------------------------------------------------
__global__ void __launch_bounds__(256)
xbf_kernel(const float* __restrict__ IN) {
    extern __shared__ unsigned short sm[];   // [128 d][128 t]

    const int tid = threadIdx.x;
    const int n0  = blockIdx.x * BT;
    const int d0  = blockIdx.y * 128;
    const int b   = n0 >> 10;
    const int hw0 = n0 & (HW_ - 1);
    const float* inb = IN + (size_t)b * (D_ * HW_) + (size_t)d0 * HW_ + hw0;

    #pragma unroll
    for (int it = 0; it < 16; ++it) {
        int j  = it * 256 + tid;
        int t4 = j & 31;
        int d  = j >> 5;
        float4 v = *reinterpret_cast<const float4*>(inb + (size_t)d * HW_ + t4 * 4);
        uint32_t* p = reinterpret_cast<uint32_t*>(&sm[d * BT + t4 * 4]);
        p[0] = (uint32_t)f2bf(v.x) | ((uint32_t)f2bf(v.y) << 16);
        p[1] = (uint32_t)f2bf(v.z) | ((uint32_t)f2bf(v.w) << 16);
    }
    __syncthreads();

    const int t    = tid & 127;
    const int half = tid >> 7;
    #pragma unroll
    for (int c = 0; c < 8; ++c) {
        int dd = half * 64 + c * 8;
        unsigned short u[8];
        #pragma unroll
        for (int i = 0; i < 8; ++i) u[i] = sm[(dd + i) * BT + t];
        uint4 q;
        q.x = (uint32_t)u[0] | ((uint32_t)u[1] << 16);
        q.y = (uint32_t)u[2] | ((uint32_t)u[3] << 16);
        q.z = (uint32_t)u[4] | ((uint32_t)u[5] << 16);
        q.w = (uint32_t)u[6] | ((uint32_t)u[7] << 16);
        *reinterpret_cast<uint4*>(&g_Xb[(size_t)(n0 + t) * D_ + d0 + dd]) = q;
    }
}

// ---------------------------------------------------------
// HMMA distance GEMM — frozen (round-13).
#define SMEM_MMA (2 * BT * APITCH * 2)

__global__ void __launch_bounds__(256, 1)
dist_mma_kernel() {
    extern __shared__ unsigned short sAB[];
    unsigned short* As = sAB;                    // [128 tok][264]
    unsigned short* Bs = sAB + BT * APITCH;      // [128 code][264]

    const int tid  = threadIdx.x;
    const int wid  = tid >> 5;
    const int lane = tid & 31;
    const int wm   = wid & 3;
    const int wn   = wid >> 2;
    const int n0   = blockIdx.x * BT;
    const int kq   = blockIdx.y;

    #pragma unroll
    for (int it = 0; it < 16; ++it) {
        int idx = it * 256 + tid;
        int row = idx >> 5, c = idx & 31;
        *reinterpret_cast<uint4*>(&As[row * APITCH + c * 8]) =
            *reinterpret_cast<const uint4*>(&g_Xb[(size_t)(n0 + row) * D_ + c * 8]);
        *reinterpret_cast<uint4*>(&Bs[row * APITCH + c * 8]) =
            *reinterpret_cast<const uint4*>(&g_Eb[(size_t)(kq * BNQ + row) * D_ + c * 8]);
    }
    __syncthreads();

    const uint32_t aBase = smem_u32(As);
    const uint32_t bBase = smem_u32(Bs);

    float acc[2][8][4];
    #pragma unroll
    for (int i = 0; i < 2; ++i)
        #pragma unroll
        for (int j = 0; j < 8; ++j)
            #pragma unroll
            for (int c = 0; c < 4; ++c) acc[i][j][c] = 0.0f;

    const int aRow = wm * 32 + (lane & 15);
    const uint32_t aOff = aBase + (uint32_t)aRow * (APITCH * 2) + (uint32_t)(lane >> 4) * 16;
    const int bRow = wn * 64 + (lane & 7) + ((lane >> 4) << 3);
    const uint32_t bOff = bBase + (uint32_t)bRow * (APITCH * 2) + (uint32_t)((lane >> 3) & 1) * 16;

    #pragma unroll
    for (int ks = 0; ks < D_ / 16; ++ks) {
        const uint32_t kb = ks * 32;
        uint32_t a[2][4];
        ldsm_x4(a[0][0], a[0][1], a[0][2], a[0][3], aOff + kb);
        ldsm_x4(a[1][0], a[1][1], a[1][2], a[1][3], aOff + 16 * (APITCH * 2) + kb);
        uint32_t bfr[8][2];
        #pragma unroll
        for (int ng = 0; ng < 4; ++ng) {
            uint32_t r0, r1, r2, r3;
            ldsm_x4(r0, r1, r2, r3, bOff + (uint32_t)ng * 16 * (APITCH * 2) + kb);
            bfr[2 * ng][0] = r0; bfr[2 * ng][1] = r1;
            bfr[2 * ng + 1][0] = r2; bfr[2 * ng + 1][1] = r3;
        }
        #pragma unroll
        for (int msub = 0; msub < 2; ++msub)
            #pragma unroll
            for (int nn = 0; nn < 8; ++nn)
                mma16816(acc[msub][nn][0], acc[msub][nn][1],
                         acc[msub][nn][2], acc[msub][nn][3],
                         a[msub][0], a[msub][1], a[msub][2], a[msub][3],
                         bfr[nn][0], bfr[nn][1]);
    }

    #pragma unroll
    for (int msub = 0; msub < 2; ++msub) {
        int tok = n0 + wm * 32 + msub * 16 + (lane >> 2);
        #pragma unroll
        for (int nn = 0; nn < 8; ++nn) {
            int code = kq * BNQ + wn * 64 + nn * 8 + 2 * (lane & 3);
            float2 en = *reinterpret_cast<const float2*>(&g_B[code]);
            float2 lo, hi;
            lo.x = fmaf(-2.0f, acc[msub][nn][0], en.x);
            lo.y = fmaf(-2.0f, acc[msub][nn][1], en.y);
            hi.x = fmaf(-2.0f, acc[msub][nn][2], en.x);
            hi.y = fmaf(-2.0f, acc[msub][nn][3], en.y);
            *reinterpret_cast<__half2*>(&g_dist[(size_t)tok * K_ + code]) =
                __float22half2_rn(lo);
            *reinterpret_cast<__half2*>(&g_dist[(size_t)(tok + 8) * K_ + code]) =
                __float22half2_rn(hi);
        }
    }
}

// ---------------------------------------------------------
__device__ __forceinline__ unsigned order_f(float f) {
    unsigned u = __float_as_uint(f);
    return (u & 0x80000000u) ? ~u : (u | 0x80000000u);
}

// select — frozen (round-13).
__global__ void __launch_bounds__(256)
select_kernel(const float* __restrict__ IN, const float* __restrict__ E) {
    const int warp = threadIdx.x >> 5;
    const int lane = threadIdx.x & 31;
    const int n = blockIdx.x * 8 + warp;

    const uint4* dr4 = reinterpret_cast<const uint4*>(g_dist + (size_t)n * K_);

    uint4 v[4];
    #pragma unroll
    for (int j = 0; j < 4; ++j) v[j] = dr4[lane + 32 * j];

    float m1 = 3.4e38f, m2 = 3.4e38f;
    int ki = 0;
    #pragma unroll
    for (int j = 0; j < 4; ++j) {
        uint32_t w[4] = {v[j].x, v[j].y, v[j].z, v[j].w};
        int kb = 8 * (lane + 32 * j);
        #pragma unroll
        for (int q = 0; q < 4; ++q) {
            float2 f = __half22float2(*reinterpret_cast<const __half2*>(&w[q]));
            if (f.x < m1) { m2 = m1; m1 = f.x; ki = kb + 2 * q; }
            else if (f.x < m2) m2 = f.x;
            if (f.y < m1) { m2 = m1; m1 = f.y; ki = kb + 2 * q + 1; }
            else if (f.y < m2) m2 = f.y;
        }
    }
    #pragma unroll
    for (int off = 16; off > 0; off >>= 1) {
        float o1 = __shfl_xor_sync(0xFFFFFFFFu, m1, off);
        float o2 = __shfl_xor_sync(0xFFFFFFFFu, m2, off);
        int   oi = __shfl_xor_sync(0xFFFFFFFFu, ki, off);
        float hi  = fmaxf(m1, o1);
        float nm2 = fminf(hi, fminf(m2, o2));
        if (o1 < m1 || (o1 == m1 && oi < ki)) ki = oi;
        m1 = fminf(m1, o1);
        m2 = nm2;
    }
    const float thresh = m1 + EPSM;

    int k_final = ki;
    if (m2 <= thresh) {
        const int b = n >> 10, hw = n & (HW_ - 1);
        const float* xb = IN + (size_t)b * (D_ * HW_) + hw;

        float xr[8];
        #pragma unroll
        for (int t = 0; t < 8; ++t)
            xr[t] = xb[(size_t)(lane + 32 * t) * HW_];

        double a = 0.0;
        #pragma unroll
        for (int t = 0; t < 8; ++t) a += (double)xr[t] * (double)xr[t];
        #pragma unroll
        for (int off = 16; off > 0; off >>= 1)
            a += __shfl_xor_sync(0xFFFFFFFFu, a, off);
        float Af = (float)a;

        unsigned cmask = 0;
        #pragma unroll
        for (int j = 0; j < 4; ++j) {
            uint32_t w[4] = {v[j].x, v[j].y, v[j].z, v[j].w};
            #pragma unroll
            for (int q = 0; q < 4; ++q) {
                float2 f = __half22float2(*reinterpret_cast<const __half2*>(&w[q]));
                if (f.x <= thresh) cmask |= 1u << (8 * j + 2 * q);
                if (f.y <= thresh) cmask |= 1u << (8 * j + 2 * q + 1);
            }
        }

        unsigned long long key = 0xFFFFFFFFFFFFFFFFull;
        while (true) {
            unsigned ball = __ballot_sync(0xFFFFFFFFu, cmask != 0);
            if (!ball) break;
            int cl = __ffs(ball) - 1;
            unsigned lm = __shfl_sync(0xFFFFFFFFu, cmask, cl);
            int bit = __ffs(lm) - 1;
            int k = 8 * (cl + 32 * (bit >> 3)) + (bit & 7);
            if (lane == cl) cmask &= cmask - 1;

            const float* er = E + (size_t)k * D_;
            double dot = 0.0;
            #pragma unroll
            for (int t = 0; t < 8; ++t)
                dot += (double)xr[t] * (double)er[lane + 32 * t];
            #pragma unroll
            for (int off = 16; off > 0; off >>= 1)
                dot += __shfl_xor_sync(0xFFFFFFFFu, dot, off);

            float Mf = (float)dot;
            float T  = Af + __ldg(&g_B[k]);   // fl32
            float ds = T - 2.0f * Mf;         // fl32
            unsigned long long kk =
                ((unsigned long long)order_f(ds) << 32) | (unsigned)k;
            if (kk < key) key = kk;
        }
        k_final = (int)(unsigned)key;
    }

    if (lane == 0) {
        g_idx[n] = k_final;
        atomicAdd(&g_counts[k_final], 1);
    }
}

// ---------------------------------------------------------
// gather: 64-token tile -> 67 KB smem -> 2 CTAs/SM, 512 blocks.
__global__ void __launch_bounds__(256)
gather_kernel(const float* __restrict__ IN, const float* __restrict__ E,
              float* __restrict__ OUT) {
    extern __shared__ float fsm[];
    float* qs   = fsm;                          // [64][257]
    int*   sidx = (int*)(fsm + BTG * 257);
    float* red  = fsm + BTG * 257 + BTG;

    const int tid = threadIdx.x;
    const int n0  = blockIdx.x * BTG;

    if (tid < BTG) sidx[tid] = g_idx[n0 + tid];
    __syncthreads();

    #pragma unroll 4
    for (int it = 0; it < BTG; ++it)
        qs[it * 257 + tid] = E[(size_t)sidx[it] * D_ + tid];
    __syncthreads();

    const int b = n0 >> 10, hw0 = n0 & (HW_ - 1);
    const size_t base = (size_t)b * (D_ * HW_) + hw0;
    float lsum = 0.0f;
    #pragma unroll 4
    for (int it = 0; it < 64; ++it) {
        int j = it * 256 + tid;
        int d = j >> 6;
        int t = j & 63;
        size_t a = base + (size_t)d * HW_ + t;
        float x = IN[a];
        float q = qs[t * 257 + d];
        OUT[a] = q;
        float df = q - x;
        lsum += df * df;
    }
    red[tid] = lsum;
    __syncthreads();
    for (int s = 128; s > 0; s >>= 1) {
        if (tid < s) red[tid] += red[tid + s];
        __syncthreads();
    }
    if (tid == 0) g_partials[blockIdx.x] = red[0];
}

// ---------------------------------------------------------
__global__ void finalize_kernel(float* __restrict__ OUT, int out_size) {
    __shared__ float red[256];
    int tid = threadIdx.x;

    red[tid] = g_partials[tid] + g_partials[tid + 256];
    __syncthreads();
    for (int s = 128; s > 0; s >>= 1) {
        if (tid < s) red[tid] += red[tid + s];
        __syncthreads();
    }
    float loss = 1.25f * red[0] / (float)NELEM_;
    __syncthreads();

    float ps = 0.0f;
    for (int i = tid; i < K_; i += 256) {
        float p = (float)g_counts[i] / (float)N_;
        ps += p * logf(p + 1e-10f);
    }
    red[tid] = ps;
    __syncthreads();
    for (int s = 128; s > 0; s >>= 1) {
        if (tid < s) red[tid] += red[tid + s];
        __syncthreads();
    }
    if (tid == 0) {
        float perp = expf(-red[0]);
        if (out_size > NELEM_)     OUT[NELEM_]     = loss;
        if (out_size > NELEM_ + 1) OUT[NELEM_ + 1] = perp;
    }
}

// ---------------------------------------------------------
extern "C" void kernel_launch(void* const* d_in, const int* in_sizes, int n_in,
                              void* d_out, int out_size) {
    const float* IN = (const float*)d_in[0];
    const float* E  = (const float*)d_in[1];
    float* OUT = (float*)d_out;

    const int smemX = 128 * BT * (int)sizeof(unsigned short);        // 32768
    const int smemM = SMEM_MMA;                                      // 135168
    const int smemC = (BTG * 257 + BTG + 256) * (int)sizeof(float);  // 67072
    cudaFuncSetAttribute(xbf_kernel,      cudaFuncAttributeMaxDynamicSharedMemorySize, smemX);
    cudaFuncSetAttribute(dist_mma_kernel, cudaFuncAttributeMaxDynamicSharedMemorySize, smemM);
    cudaFuncSetAttribute(gather_kernel,   cudaFuncAttributeMaxDynamicSharedMemorySize, smemC);

    prep_kernel<<<K_, 256>>>(E);
    xbf_kernel<<<dim3(N_ / BT, 2), 256, smemX>>>(IN);
    dist_mma_kernel<<<dim3(N_ / BT, K_ / BNQ), 256, smemM>>>();
    select_kernel<<<N_ / 8, 256>>>(IN, E);
    gather_kernel<<<N_ / BTG, 256, smemC>>>(IN, E, OUT);
    finalize_kernel<<<1, 256>>>(OUT, out_size);
}

// round 15
// speedup vs baseline: 1.4222x; 1.0030x over previous
#include <cuda_runtime.h>
#include <cuda_bf16.h>
#include <cuda_fp16.h>
#include <cstdint>
#include <math.h>

#define D_    256
#define HW_   1024
#define N_    32768
#define K_    1024
#define NELEM_ 8388608
#define BT    128
#define BNQ   128
#define BTG   64
#define EPSM  1e-3f

#define APITCH 264

// -------- device scratch --------
__device__ __half         g_dist[N_ * (size_t)K_];  // 64 MiB fp16 approx distances
__device__ float          g_B[K_];
__device__ int            g_idx[N_];
__device__ int            g_counts[K_];
__device__ float          g_partials[N_ / BTG];
__device__ unsigned short g_Xb[N_ * D_];
__device__ unsigned short g_Eb[K_ * D_];

// -------- helpers --------
__device__ __forceinline__ unsigned short f2bf(float x) {
    __nv_bfloat16 b = __float2bfloat16(x);
    return *reinterpret_cast<unsigned short*>(&b);
}
__device__ __forceinline__ uint32_t smem_u32(const void* p) {
    uint32_t a;
    asm("{ .reg .u64 t; cvta.to.shared.u64 t, %1; cvt.u32.u64 %0, t; }" : "=r"(a) : "l"(p));
    return a;
}
__device__ __forceinline__ void ldsm_x4(uint32_t& r0, uint32_t& r1,
                                        uint32_t& r2, uint32_t& r3, uint32_t addr) {
    asm volatile("ldmatrix.sync.aligned.m8n8.x4.shared.b16 {%0,%1,%2,%3}, [%4];"
                 : "=r"(r0), "=r"(r1), "=r"(r2), "=r"(r3) : "r"(addr));
}
__device__ __forceinline__ void mma16816(float& c0, float& c1, float& c2, float& c3,
                                         uint32_t a0, uint32_t a1, uint32_t a2, uint32_t a3,
                                         uint32_t b0, uint32_t b1) {
    asm volatile(
        "mma.sync.aligned.m16n8k16.row.col.f32.bf16.bf16.f32 "
        "{%0,%1,%2,%3}, {%4,%5,%6,%7}, {%8,%9}, {%0,%1,%2,%3};"
        : "+f"(c0), "+f"(c1), "+f"(c2), "+f"(c3)
        : "r"(a0), "r"(a1), "r"(a2), "r"(a3), "r"(b0), "r"(b1));
}

// ---------------------------------------------------------
// Merged prep: per code k -> g_Eb (bf16), g_B (f64 norm), g_counts=0.
__global__ void prep_kernel(const float* __restrict__ E) {
    __shared__ double red[256];
    int k = blockIdx.x;
    float v = E[(size_t)k * D_ + threadIdx.x];
    g_Eb[k * D_ + threadIdx.x] = f2bf(v);
    red[threadIdx.x] = (double)v * (double)v;
    __syncthreads();
    for (int s = 128; s > 0; s >>= 1) {
        if (threadIdx.x < s) red[threadIdx.x] += red[threadIdx.x + s];
        __syncthreads();
    }
    if (threadIdx.x == 0) {
        g_B[k] = (float)red[0];
        g_counts[k] = 0;
    }
}

// ---------------------------------------------------------
__global__ void __launch_bounds__(256)
xbf_kernel(const float* __restrict__ IN) {
    extern __shared__ unsigned short sm[];   // [128 d][128 t]

    const int tid = threadIdx.x;
    const int n0  = blockIdx.x * BT;
    const int d0  = blockIdx.y * 128;
    const int b   = n0 >> 10;
    const int hw0 = n0 & (HW_ - 1);
    const float* inb = IN + (size_t)b * (D_ * HW_) + (size_t)d0 * HW_ + hw0;

    #pragma unroll
    for (int it = 0; it < 16; ++it) {
        int j  = it * 256 + tid;
        int t4 = j & 31;
        int d  = j >> 5;
        float4 v = *reinterpret_cast<const float4*>(inb + (size_t)d * HW_ + t4 * 4);
        uint32_t* p = reinterpret_cast<uint32_t*>(&sm[d * BT + t4 * 4]);
        p[0] = (uint32_t)f2bf(v.x) | ((uint32_t)f2bf(v.y) << 16);
        p[1] = (uint32_t)f2bf(v.z) | ((uint32_t)f2bf(v.w) << 16);
    }
    __syncthreads();

    const int t    = tid & 127;
    const int half = tid >> 7;
    #pragma unroll
    for (int c = 0; c < 8; ++c) {
        int dd = half * 64 + c * 8;
        unsigned short u[8];
        #pragma unroll
        for (int i = 0; i < 8; ++i) u[i] = sm[(dd + i) * BT + t];
        uint4 q;
        q.x = (uint32_t)u[0] | ((uint32_t)u[1] << 16);
        q.y = (uint32_t)u[2] | ((uint32_t)u[3] << 16);
        q.z = (uint32_t)u[4] | ((uint32_t)u[5] << 16);
        q.w = (uint32_t)u[6] | ((uint32_t)u[7] << 16);
        *reinterpret_cast<uint4*>(&g_Xb[(size_t)(n0 + t) * D_ + d0 + dd]) = q;
    }
}

// ---------------------------------------------------------
// HMMA distance GEMM — frozen (round-13).
#define SMEM_MMA (2 * BT * APITCH * 2)

__global__ void __launch_bounds__(256, 1)
dist_mma_kernel() {
    extern __shared__ unsigned short sAB[];
    unsigned short* As = sAB;                    // [128 tok][264]
    unsigned short* Bs = sAB + BT * APITCH;      // [128 code][264]

    const int tid  = threadIdx.x;
    const int wid  = tid >> 5;
    const int lane = tid & 31;
    const int wm   = wid & 3;
    const int wn   = wid >> 2;
    const int n0   = blockIdx.x * BT;
    const int kq   = blockIdx.y;

    #pragma unroll
    for (int it = 0; it < 16; ++it) {
        int idx = it * 256 + tid;
        int row = idx >> 5, c = idx & 31;
        *reinterpret_cast<uint4*>(&As[row * APITCH + c * 8]) =
            *reinterpret_cast<const uint4*>(&g_Xb[(size_t)(n0 + row) * D_ + c * 8]);
        *reinterpret_cast<uint4*>(&Bs[row * APITCH + c * 8]) =
            *reinterpret_cast<const uint4*>(&g_Eb[(size_t)(kq * BNQ + row) * D_ + c * 8]);
    }
    __syncthreads();

    const uint32_t aBase = smem_u32(As);
    const uint32_t bBase = smem_u32(Bs);

    float acc[2][8][4];
    #pragma unroll
    for (int i = 0; i < 2; ++i)
        #pragma unroll
        for (int j = 0; j < 8; ++j)
            #pragma unroll
            for (int c = 0; c < 4; ++c) acc[i][j][c] = 0.0f;

    const int aRow = wm * 32 + (lane & 15);
    const uint32_t aOff = aBase + (uint32_t)aRow * (APITCH * 2) + (uint32_t)(lane >> 4) * 16;
    const int bRow = wn * 64 + (lane & 7) + ((lane >> 4) << 3);
    const uint32_t bOff = bBase + (uint32_t)bRow * (APITCH * 2) + (uint32_t)((lane >> 3) & 1) * 16;

    #pragma unroll
    for (int ks = 0; ks < D_ / 16; ++ks) {
        const uint32_t kb = ks * 32;
        uint32_t a[2][4];
        ldsm_x4(a[0][0], a[0][1], a[0][2], a[0][3], aOff + kb);
        ldsm_x4(a[1][0], a[1][1], a[1][2], a[1][3], aOff + 16 * (APITCH * 2) + kb);
        uint32_t bfr[8][2];
        #pragma unroll
        for (int ng = 0; ng < 4; ++ng) {
            uint32_t r0, r1, r2, r3;
            ldsm_x4(r0, r1, r2, r3, bOff + (uint32_t)ng * 16 * (APITCH * 2) + kb);
            bfr[2 * ng][0] = r0; bfr[2 * ng][1] = r1;
            bfr[2 * ng + 1][0] = r2; bfr[2 * ng + 1][1] = r3;
        }
        #pragma unroll
        for (int msub = 0; msub < 2; ++msub)
            #pragma unroll
            for (int nn = 0; nn < 8; ++nn)
                mma16816(acc[msub][nn][0], acc[msub][nn][1],
                         acc[msub][nn][2], acc[msub][nn][3],
                         a[msub][0], a[msub][1], a[msub][2], a[msub][3],
                         bfr[nn][0], bfr[nn][1]);
    }

    #pragma unroll
    for (int msub = 0; msub < 2; ++msub) {
        int tok = n0 + wm * 32 + msub * 16 + (lane >> 2);
        #pragma unroll
        for (int nn = 0; nn < 8; ++nn) {
            int code = kq * BNQ + wn * 64 + nn * 8 + 2 * (lane & 3);
            float2 en = *reinterpret_cast<const float2*>(&g_B[code]);
            float2 lo, hi;
            lo.x = fmaf(-2.0f, acc[msub][nn][0], en.x);
            lo.y = fmaf(-2.0f, acc[msub][nn][1], en.y);
            hi.x = fmaf(-2.0f, acc[msub][nn][2], en.x);
            hi.y = fmaf(-2.0f, acc[msub][nn][3], en.y);
            *reinterpret_cast<__half2*>(&g_dist[(size_t)tok * K_ + code]) =
                __float22half2_rn(lo);
            *reinterpret_cast<__half2*>(&g_dist[(size_t)(tok + 8) * K_ + code]) =
                __float22half2_rn(hi);
        }
    }
}

// ---------------------------------------------------------
__device__ __forceinline__ unsigned order_f(float f) {
    unsigned u = __float_as_uint(f);
    return (u & 0x80000000u) ? ~u : (u | 0x80000000u);
}

// select v5: fp16-domain SIMD min (__hmin2 tree) + __hle2 candidate mask.
// Fast path iff exactly one candidate warp-wide; else exact fp64 re-score.
__global__ void __launch_bounds__(256)
select_kernel(const float* __restrict__ IN, const float* __restrict__ E) {
    const int warp = threadIdx.x >> 5;
    const int lane = threadIdx.x & 31;
    const int n = blockIdx.x * 8 + warp;

    const uint4* dr4 = reinterpret_cast<const uint4*>(g_dist + (size_t)n * K_);

    uint4 v[4];
    #pragma unroll
    for (int j = 0; j < 4; ++j) v[j] = dr4[lane + 32 * j];   // 4 independent LDG.128

    // --- min via __hmin2 tree (no unpack) ---
    __half2 m2h = *reinterpret_cast<const __half2*>(&v[0].x);
    #pragma unroll
    for (int j = 0; j < 4; ++j) {
        const uint32_t w[4] = {v[j].x, v[j].y, v[j].z, v[j].w};
        #pragma unroll
        for (int q = 0; q < 4; ++q) {
            if (j == 0 && q == 0) continue;
            m2h = __hmin2(m2h, *reinterpret_cast<const __half2*>(&w[q]));
        }
    }
    float m1 = fminf(__half2float(__low2half(m2h)), __half2float(__high2half(m2h)));
    #pragma unroll
    for (int off = 16; off > 0; off >>= 1)
        m1 = fminf(m1, __shfl_xor_sync(0xFFFFFFFFu, m1, off));

    // --- candidate mask vs round-up fp16 threshold (superset of float net) ---
    const __half th = __float2half_ru(m1 + EPSM);
    const __half2 th2 = __half2half2(th);
    unsigned cmask = 0;        // bit 8j+p -> code 8*(lane+32j)+p
    #pragma unroll
    for (int j = 0; j < 4; ++j) {
        const uint32_t w[4] = {v[j].x, v[j].y, v[j].z, v[j].w};
        #pragma unroll
        for (int q = 0; q < 4; ++q) {
            __half2 c = __hle2(*reinterpret_cast<const __half2*>(&w[q]), th2);
            uint32_t cu = *reinterpret_cast<uint32_t*>(&c);
            if (cu & 0x0000FFFFu) cmask |= 1u << (8 * j + 2 * q);
            if (cu & 0xFFFF0000u) cmask |= 1u << (8 * j + 2 * q + 1);
        }
    }
    int tot = __popc(cmask);
    #pragma unroll
    for (int off = 16; off > 0; off >>= 1)
        tot += __shfl_xor_sync(0xFFFFFFFFu, tot, off);

    int k_final;
    if (tot == 1) {
        unsigned ball = __ballot_sync(0xFFFFFFFFu, cmask != 0);
        int cl = __ffs(ball) - 1;
        unsigned lm = __shfl_sync(0xFFFFFFFFu, cmask, cl);
        int bit = __ffs(lm) - 1;
        k_final = 8 * (cl + 32 * (bit >> 3)) + (bit & 7);
    } else {
        // exact fp32-rounding emulation over candidates (warp-cooperative)
        const int b = n >> 10, hw = n & (HW_ - 1);
        const float* xb = IN + (size_t)b * (D_ * HW_) + hw;

        float xr[8];
        #pragma unroll
        for (int t = 0; t < 8; ++t)
            xr[t] = xb[(size_t)(lane + 32 * t) * HW_];

        double a = 0.0;
        #pragma unroll
        for (int t = 0; t < 8; ++t) a += (double)xr[t] * (double)xr[t];
        #pragma unroll
        for (int off = 16; off > 0; off >>= 1)
            a += __shfl_xor_sync(0xFFFFFFFFu, a, off);
        float Af = (float)a;

        unsigned long long key = 0xFFFFFFFFFFFFFFFFull;
        while (true) {
            unsigned ball = __ballot_sync(0xFFFFFFFFu, cmask != 0);
            if (!ball) break;
            int cl = __ffs(ball) - 1;
            unsigned lm = __shfl_sync(0xFFFFFFFFu, cmask, cl);
            int bit = __ffs(lm) - 1;
            int k = 8 * (cl + 32 * (bit >> 3)) + (bit & 7);
            if (lane == cl) cmask &= cmask - 1;

            const float* er = E + (size_t)k * D_;
            double dot = 0.0;
            #pragma unroll
            for (int t = 0; t < 8; ++t)
                dot += (double)xr[t] * (double)er[lane + 32 * t];
            #pragma unroll
            for (int off = 16; off > 0; off >>= 1)
                dot += __shfl_xor_sync(0xFFFFFFFFu, dot, off);

            float Mf = (float)dot;
            float T  = Af + __ldg(&g_B[k]);   // fl32
            float ds = T - 2.0f * Mf;         // fl32
            unsigned long long kk =
                ((unsigned long long)order_f(ds) << 32) | (unsigned)k;
            if (kk < key) key = kk;
        }
        k_final = (int)(unsigned)key;
    }

    if (lane == 0) {
        g_idx[n] = k_final;
        atomicAdd(&g_counts[k_final], 1);
    }
}

// ---------------------------------------------------------
// gather: 64-token tile -> 67 KB smem -> 2 CTAs/SM, 512 blocks.
__global__ void __launch_bounds__(256)
gather_kernel(const float* __restrict__ IN, const float* __restrict__ E,
              float* __restrict__ OUT) {
    extern __shared__ float fsm[];
    float* qs   = fsm;                          // [64][257]
    int*   sidx = (int*)(fsm + BTG * 257);
    float* red  = fsm + BTG * 257 + BTG;

    const int tid = threadIdx.x;
    const int n0  = blockIdx.x * BTG;

    if (tid < BTG) sidx[tid] = g_idx[n0 + tid];
    __syncthreads();

    #pragma unroll 4
    for (int it = 0; it < BTG; ++it)
        qs[it * 257 + tid] = E[(size_t)sidx[it] * D_ + tid];
    __syncthreads();

    const int b = n0 >> 10, hw0 = n0 & (HW_ - 1);
    const size_t base = (size_t)b * (D_ * HW_) + hw0;
    float lsum = 0.0f;
    #pragma unroll 4
    for (int it = 0; it < 64; ++it) {
        int j = it * 256 + tid;
        int d = j >> 6;
        int t = j & 63;
        size_t a = base + (size_t)d * HW_ + t;
        float x = IN[a];
        float q = qs[t * 257 + d];
        OUT[a] = q;
        float df = q - x;
        lsum += df * df;
    }
    red[tid] = lsum;
    __syncthreads();
    for (int s = 128; s > 0; s >>= 1) {
        if (tid < s) red[tid] += red[tid + s];
        __syncthreads();
    }
    if (tid == 0) g_partials[blockIdx.x] = red[0];
}

// ---------------------------------------------------------
__global__ void finalize_kernel(float* __restrict__ OUT, int out_size) {
    __shared__ float red[256];
    int tid = threadIdx.x;

    red[tid] = g_partials[tid] + g_partials[tid + 256];
    __syncthreads();
    for (int s = 128; s > 0; s >>= 1) {
        if (tid < s) red[tid] += red[tid + s];
        __syncthreads();
    }
    float loss = 1.25f * red[0] / (float)NELEM_;
    __syncthreads();

    float ps = 0.0f;
    for (int i = tid; i < K_; i += 256) {
        float p = (float)g_counts[i] / (float)N_;
        ps += p * logf(p + 1e-10f);
    }
    red[tid] = ps;
    __syncthreads();
    for (int s = 128; s > 0; s >>= 1) {
        if (tid < s) red[tid] += red[tid + s];
        __syncthreads();
    }
    if (tid == 0) {
        float perp = expf(-red[0]);
        if (out_size > NELEM_)     OUT[NELEM_]     = loss;
        if (out_size > NELEM_ + 1) OUT[NELEM_ + 1] = perp;
    }
}

// ---------------------------------------------------------
extern "C" void kernel_launch(void* const* d_in, const int* in_sizes, int n_in,
                              void* d_out, int out_size) {
    const float* IN = (const float*)d_in[0];
    const float* E  = (const float*)d_in[1];
    float* OUT = (float*)d_out;

    const int smemX = 128 * BT * (int)sizeof(unsigned short);        // 32768
    const int smemM = SMEM_MMA;                                      // 135168
    const int smemC = (BTG * 257 + BTG + 256) * (int)sizeof(float);  // 67072
    cudaFuncSetAttribute(xbf_kernel,      cudaFuncAttributeMaxDynamicSharedMemorySize, smemX);
    cudaFuncSetAttribute(dist_mma_kernel, cudaFuncAttributeMaxDynamicSharedMemorySize, smemM);
    cudaFuncSetAttribute(gather_kernel,   cudaFuncAttributeMaxDynamicSharedMemorySize, smemC);

    prep_kernel<<<K_, 256>>>(E);
    xbf_kernel<<<dim3(N_ / BT, 2), 256, smemX>>>(IN);
    dist_mma_kernel<<<dim3(N_ / BT, K_ / BNQ), 256, smemM>>>();
    select_kernel<<<N_ / 8, 256>>>(IN, E);
    gather_kernel<<<N_ / BTG, 256, smemC>>>(IN, E, OUT);
    finalize_kernel<<<1, 256>>>(OUT, out_size);
}